// round 2
// baseline (speedup 1.0000x reference)
#include <cuda_runtime.h>
#include <math.h>

#define SEQ    4096
#define DIM    1024
#define NH     16
#define HD     64
#define HIDDEN 4096

// ---------------- scratch (static device arrays; no allocation in kernel_launch) ---
__device__ float g_xn[SEQ * DIM];
__device__ float g_q [SEQ * DIM];
__device__ float g_k [SEQ * DIM];
__device__ float g_v [SEQ * DIM];
__device__ float g_at[SEQ * DIM];
__device__ float g_hn[SEQ * DIM];
__device__ float g_t1[SEQ * HIDDEN];
__device__ float g_t3[SEQ * HIDDEN];
__device__ float g_cos[SEQ * (HD / 2)];
__device__ float g_sin[SEQ * (HD / 2)];

// ---------------- RoPE tables in double precision ---------------------------------
__global__ void rope_tables_k(float* __restrict__ c, float* __restrict__ s) {
    int idx = blockIdx.x * blockDim.x + threadIdx.x;   // SEQ*32
    int pos = idx >> 5;
    int i   = idx & 31;
    double inv = exp(-((double)(2 * i) / (double)HD) * log(10000.0));
    double ang = (double)pos * inv;
    double cs, sn;
    sincos(ang, &sn, &cs);
    c[idx] = (float)cs;
    s[idx] = (float)sn;
}

// ---------------- RMSNorm: one block per row (1024 cols, 256 threads x float4) ----
__global__ void rmsnorm_k(const float* __restrict__ x, const float* __restrict__ g,
                          float* __restrict__ o) {
    int row = blockIdx.x;
    const float4* xr = (const float4*)(x + (size_t)row * DIM);
    float4*       orow = (float4*)(o + (size_t)row * DIM);
    int t = threadIdx.x;                       // 256 threads
    float4 v = xr[t];
    float ss = v.x * v.x + v.y * v.y + v.z * v.z + v.w * v.w;
    #pragma unroll
    for (int off = 16; off; off >>= 1) ss += __shfl_xor_sync(0xffffffffu, ss, off);
    __shared__ float sp[8];
    if ((t & 31) == 0) sp[t >> 5] = ss;
    __syncthreads();
    if (t < 8) {
        float s2 = sp[t];
        #pragma unroll
        for (int off = 4; off; off >>= 1) s2 += __shfl_xor_sync(0xffu, s2, off);
        if (t == 0) sp[0] = s2;
    }
    __syncthreads();
    float rs = rsqrtf(sp[0] * (1.0f / DIM) + 1e-6f);
    float4 gg = ((const float4*)g)[t];
    float4 out;
    out.x = v.x * rs * gg.x;
    out.y = v.y * rs * gg.y;
    out.z = v.z * rs * gg.z;
    out.w = v.w * rs * gg.w;
    orow[t] = out;
}

// ---------------- GEMM: C[M,N] = A[M,K] @ B[N,K]^T (+ optional residual) ---------
// 128x128 tile, BK=16, 256 threads, 8x8 register tile per thread.
#define BM 128
#define BN 128
#define BK 16
#define TM 8
#define TN 8

template <bool RESID>
__global__ __launch_bounds__(256)
void gemm_tn(const float* __restrict__ A, const float* __restrict__ B,
             const float* __restrict__ res, float* __restrict__ C,
             int M, int N, int K) {
    __shared__ float As[BK][BM];
    __shared__ float Bs[BK][BN];

    const int bm = blockIdx.y * BM;
    const int bn = blockIdx.x * BN;
    const int tid = threadIdx.x;

    float acc[TM][TN];
    #pragma unroll
    for (int i = 0; i < TM; i++)
        #pragma unroll
        for (int j = 0; j < TN; j++) acc[i][j] = 0.0f;

    const int tmr = (tid >> 4) * TM;   // 0..120
    const int tnr = (tid & 15) * TN;   // 0..120

    for (int k0 = 0; k0 < K; k0 += BK) {
        #pragma unroll
        for (int i = 0; i < 2; i++) {
            int idx = tid + i * 256;          // 0..511 over 128 rows x 4 float4
            int row = idx >> 2;
            int c4  = (idx & 3) * 4;
            float4 a = *(const float4*)&A[(size_t)(bm + row) * K + k0 + c4];
            As[c4 + 0][row] = a.x; As[c4 + 1][row] = a.y;
            As[c4 + 2][row] = a.z; As[c4 + 3][row] = a.w;
            float4 b = *(const float4*)&B[(size_t)(bn + row) * K + k0 + c4];
            Bs[c4 + 0][row] = b.x; Bs[c4 + 1][row] = b.y;
            Bs[c4 + 2][row] = b.z; Bs[c4 + 3][row] = b.w;
        }
        __syncthreads();

        #pragma unroll
        for (int kk = 0; kk < BK; kk++) {
            float ra[TM], rb[TN];
            #pragma unroll
            for (int i = 0; i < TM; i += 4) {
                float4 t4 = *(const float4*)&As[kk][tmr + i];
                ra[i] = t4.x; ra[i + 1] = t4.y; ra[i + 2] = t4.z; ra[i + 3] = t4.w;
            }
            #pragma unroll
            for (int j = 0; j < TN; j += 4) {
                float4 t4 = *(const float4*)&Bs[kk][tnr + j];
                rb[j] = t4.x; rb[j + 1] = t4.y; rb[j + 2] = t4.z; rb[j + 3] = t4.w;
            }
            #pragma unroll
            for (int i = 0; i < TM; i++)
                #pragma unroll
                for (int j = 0; j < TN; j++)
                    acc[i][j] = fmaf(ra[i], rb[j], acc[i][j]);
        }
        __syncthreads();
    }

    #pragma unroll
    for (int i = 0; i < TM; i++) {
        size_t rbase = (size_t)(bm + tmr + i) * N + bn + tnr;
        #pragma unroll
        for (int j = 0; j < TN; j += 4) {
            float4 v4;
            v4.x = acc[i][j + 0]; v4.y = acc[i][j + 1];
            v4.z = acc[i][j + 2]; v4.w = acc[i][j + 3];
            if (RESID) {
                float4 r4 = *(const float4*)&res[rbase + j];
                v4.x += r4.x; v4.y += r4.y; v4.z += r4.z; v4.w += r4.w;
            }
            *(float4*)&C[rbase + j] = v4;
        }
    }
}

// ---------------- RoPE on q and k in-place (table-driven) --------------------------
// grid = SEQ blocks, 512 threads = 16 heads x 32 pairs
__global__ void rope_k(float* __restrict__ q, float* __restrict__ k,
                       const float* __restrict__ ct, const float* __restrict__ st) {
    int pos = blockIdx.x;
    int t = threadIdx.x;
    int h = t >> 5;
    int i = t & 31;
    float c = ct[pos * 32 + i];
    float s = st[pos * 32 + i];
    size_t base = (size_t)pos * DIM + h * HD + 2 * i;
    float2 qq = *(float2*)&q[base];
    float2 qo; qo.x = qq.x * c - qq.y * s; qo.y = qq.x * s + qq.y * c;
    *(float2*)&q[base] = qo;
    float2 kk = *(float2*)&k[base];
    float2 ko; ko.x = kk.x * c - kk.y * s; ko.y = kk.x * s + kk.y * c;
    *(float2*)&k[base] = ko;
}

// ---------------- Flash attention (non-causal), fp32 -------------------------------
// grid = (SEQ/128, NH); 128 threads; thread = one query row; K/V tiles of 32 in smem.
#define AQ 128
#define AK 32

__global__ __launch_bounds__(128)
void flash_attn(const float* __restrict__ Q, const float* __restrict__ K,
                const float* __restrict__ V, float* __restrict__ O) {
    const int h  = blockIdx.y;
    const int q0 = blockIdx.x * AQ;
    const int t  = threadIdx.x;
    const float scale = 0.125f;   // 1/sqrt(64)

    __shared__ float Ks[AK][HD];
    __shared__ float Vs[AK][HD];

    float qreg[HD];
    float o[HD];
    float m = -1e30f, l = 0.0f;

    const float* qp = Q + (size_t)(q0 + t) * DIM + h * HD;
    #pragma unroll
    for (int d = 0; d < HD; d += 4) {
        float4 v4 = *(const float4*)(qp + d);
        qreg[d] = v4.x * scale; qreg[d + 1] = v4.y * scale;
        qreg[d + 2] = v4.z * scale; qreg[d + 3] = v4.w * scale;
        o[d] = 0.f; o[d + 1] = 0.f; o[d + 2] = 0.f; o[d + 3] = 0.f;
    }

    for (int k0 = 0; k0 < SEQ; k0 += AK) {
        __syncthreads();
        #pragma unroll
        for (int i = 0; i < 4; i++) {
            int idx = t + i * 128;            // 0..511 -> 32 rows x 16 float4
            int row = idx >> 4;
            int c   = (idx & 15) * 4;
            *(float4*)&Ks[row][c] = *(const float4*)&K[(size_t)(k0 + row) * DIM + h * HD + c];
            *(float4*)&Vs[row][c] = *(const float4*)&V[(size_t)(k0 + row) * DIM + h * HD + c];
        }
        __syncthreads();

        float s[AK];
        float tmax = -1e30f;
        #pragma unroll
        for (int j = 0; j < AK; j++) {
            float acc = 0.0f;
            #pragma unroll
            for (int d = 0; d < HD; d += 4) {
                float4 kv = *(const float4*)&Ks[j][d];
                acc = fmaf(qreg[d], kv.x, acc);
                acc = fmaf(qreg[d + 1], kv.y, acc);
                acc = fmaf(qreg[d + 2], kv.z, acc);
                acc = fmaf(qreg[d + 3], kv.w, acc);
            }
            s[j] = acc;
            tmax = fmaxf(tmax, acc);
        }

        float mnew = fmaxf(m, tmax);
        float corr = __expf(m - mnew);
        l *= corr;
        #pragma unroll
        for (int d = 0; d < HD; d++) o[d] *= corr;
        m = mnew;

        #pragma unroll
        for (int j = 0; j < AK; j++) {
            float p = __expf(s[j] - mnew);
            l += p;
            #pragma unroll
            for (int d = 0; d < HD; d += 4) {
                float4 vv = *(const float4*)&Vs[j][d];
                o[d]     = fmaf(p, vv.x, o[d]);
                o[d + 1] = fmaf(p, vv.y, o[d + 1]);
                o[d + 2] = fmaf(p, vv.z, o[d + 2]);
                o[d + 3] = fmaf(p, vv.w, o[d + 3]);
            }
        }
    }

    float invl = 1.0f / l;
    float* op = O + (size_t)(q0 + t) * DIM + h * HD;
    #pragma unroll
    for (int d = 0; d < HD; d += 4) {
        float4 v4;
        v4.x = o[d] * invl; v4.y = o[d + 1] * invl;
        v4.z = o[d + 2] * invl; v4.w = o[d + 3] * invl;
        *(float4*)(op + d) = v4;
    }
}

// ---------------- SwiGLU elementwise: a = silu(a) * b -------------------------------
__global__ void silu_mul_k(float* __restrict__ a, const float* __restrict__ b, int n4) {
    int i = blockIdx.x * blockDim.x + threadIdx.x;
    if (i < n4) {
        float4 x = ((float4*)a)[i];
        float4 y = ((const float4*)b)[i];
        x.x = x.x / (1.0f + __expf(-x.x)) * y.x;
        x.y = x.y / (1.0f + __expf(-x.y)) * y.y;
        x.z = x.z / (1.0f + __expf(-x.z)) * y.z;
        x.w = x.w / (1.0f + __expf(-x.w)) * y.w;
        ((float4*)a)[i] = x;
    }
}

// ---------------- launch -----------------------------------------------------------
extern "C" void kernel_launch(void* const* d_in, const int* in_sizes, int n_in,
                              void* d_out, int out_size) {
    const float* x  = (const float*)d_in[0];
    const float* wq = (const float*)d_in[1];
    const float* wk = (const float*)d_in[2];
    const float* wv = (const float*)d_in[3];
    const float* wo = (const float*)d_in[4];
    const float* w1 = (const float*)d_in[5];
    const float* w2 = (const float*)d_in[6];
    const float* w3 = (const float*)d_in[7];
    const float* ga = (const float*)d_in[8];
    const float* gf = (const float*)d_in[9];
    float* out = (float*)d_out;

    float *xn, *q, *k, *v, *at, *hn, *t1, *t3, *ct, *st;
    cudaGetSymbolAddress((void**)&xn, g_xn);
    cudaGetSymbolAddress((void**)&q,  g_q);
    cudaGetSymbolAddress((void**)&k,  g_k);
    cudaGetSymbolAddress((void**)&v,  g_v);
    cudaGetSymbolAddress((void**)&at, g_at);
    cudaGetSymbolAddress((void**)&hn, g_hn);
    cudaGetSymbolAddress((void**)&t1, g_t1);
    cudaGetSymbolAddress((void**)&t3, g_t3);
    cudaGetSymbolAddress((void**)&ct, g_cos);
    cudaGetSymbolAddress((void**)&st, g_sin);

    // 0) RoPE tables (double precision)
    rope_tables_k<<<(SEQ * 32) / 256, 256>>>(ct, st);

    // 1) attn RMSNorm
    rmsnorm_k<<<SEQ, 256>>>(x, ga, xn);

    // 2) QKV projections
    dim3 g1(DIM / BN, SEQ / BM);
    gemm_tn<false><<<g1, 256>>>(xn, wq, nullptr, q, SEQ, DIM, DIM);
    gemm_tn<false><<<g1, 256>>>(xn, wk, nullptr, k, SEQ, DIM, DIM);
    gemm_tn<false><<<g1, 256>>>(xn, wv, nullptr, v, SEQ, DIM, DIM);

    // 3) RoPE on q, k
    rope_k<<<SEQ, 512>>>(q, k, ct, st);

    // 4) attention
    flash_attn<<<dim3(SEQ / AQ, NH), 128>>>(q, k, v, at);

    // 5) output projection + residual -> h (in d_out)
    gemm_tn<true><<<g1, 256>>>(at, wo, x, out, SEQ, DIM, DIM);

    // 6) ffn RMSNorm
    rmsnorm_k<<<SEQ, 256>>>(out, gf, hn);

    // 7) w1 / w3 GEMMs
    dim3 g2(HIDDEN / BN, SEQ / BM);
    gemm_tn<false><<<g2, 256>>>(hn, w1, nullptr, t1, SEQ, HIDDEN, DIM);
    gemm_tn<false><<<g2, 256>>>(hn, w3, nullptr, t3, SEQ, HIDDEN, DIM);

    // 8) silu(t1) * t3 -> t1
    silu_mul_k<<<(SEQ * HIDDEN / 4 + 255) / 256, 256>>>(t1, t3, SEQ * HIDDEN / 4);

    // 9) down-projection + residual (in-place on d_out)
    gemm_tn<true><<<g1, 256>>>(t1, w2, out, out, SEQ, DIM, HIDDEN);
}

// round 3
// speedup vs baseline: 1.6652x; 1.6652x over previous
#include <cuda_runtime.h>
#include <math.h>
#include <stdint.h>

#define SEQ    4096
#define DIM    1024
#define NH     16
#define HD     64
#define HIDDEN 4096

// ---------------- scratch (static device arrays; no allocation in kernel_launch) ---
__device__ float g_xn[SEQ * DIM];
__device__ float g_q [SEQ * DIM];
__device__ float g_k [SEQ * DIM];
__device__ float g_v [SEQ * DIM];
__device__ float g_at[SEQ * DIM];
__device__ float g_hn[SEQ * DIM];
__device__ float g_t1[SEQ * HIDDEN];
__device__ float g_t3[SEQ * HIDDEN];
__device__ float g_cos[SEQ * (HD / 2)];
__device__ float g_sin[SEQ * (HD / 2)];

// ---------------- RoPE tables in double precision ---------------------------------
__global__ void rope_tables_k(float* __restrict__ c, float* __restrict__ s) {
    int idx = blockIdx.x * blockDim.x + threadIdx.x;   // SEQ*32
    int pos = idx >> 5;
    int i   = idx & 31;
    double inv = exp(-((double)(2 * i) / (double)HD) * log(10000.0));
    double ang = (double)pos * inv;
    double cs, sn;
    sincos(ang, &sn, &cs);
    c[idx] = (float)cs;
    s[idx] = (float)sn;
}

// ---------------- RMSNorm ----------------------------------------------------------
__global__ void rmsnorm_k(const float* __restrict__ x, const float* __restrict__ g,
                          float* __restrict__ o) {
    int row = blockIdx.x;
    const float4* xr = (const float4*)(x + (size_t)row * DIM);
    float4*       orow = (float4*)(o + (size_t)row * DIM);
    int t = threadIdx.x;                       // 256 threads
    float4 v = xr[t];
    float ss = v.x * v.x + v.y * v.y + v.z * v.z + v.w * v.w;
    #pragma unroll
    for (int off = 16; off; off >>= 1) ss += __shfl_xor_sync(0xffffffffu, ss, off);
    __shared__ float sp[8];
    if ((t & 31) == 0) sp[t >> 5] = ss;
    __syncthreads();
    if (t < 8) {
        float s2 = sp[t];
        #pragma unroll
        for (int off = 4; off; off >>= 1) s2 += __shfl_xor_sync(0xffu, s2, off);
        if (t == 0) sp[0] = s2;
    }
    __syncthreads();
    float rs = rsqrtf(sp[0] * (1.0f / DIM) + 1e-6f);
    float4 gg = ((const float4*)g)[t];
    float4 out;
    out.x = v.x * rs * gg.x;
    out.y = v.y * rs * gg.y;
    out.z = v.z * rs * gg.z;
    out.w = v.w * rs * gg.w;
    orow[t] = out;
}

// ---------------- tf32 tensor-core GEMM: C[M,N] = A[M,K] @ B[N,K]^T (+res) --------
// CTA tile 128x128, BK=16, 256 threads = 8 warps (2 x 4), warp tile 64x32.
// mma.sync.m16n8k8 tf32. Double-buffered smem, stride-20 padding (conflict-free).
#define BM 128
#define BN 128
#define BK 16
#define SST 20   // smem row stride (floats)

__device__ __forceinline__ uint32_t f2tf32(float f) {
    uint32_t u;
    asm("cvt.rna.tf32.f32 %0, %1;" : "=r"(u) : "f"(f));
    return u;
}

template <bool RESID>
__global__ __launch_bounds__(256, 2)
void gemm_tf32(const float* __restrict__ A, const float* __restrict__ B,
               const float* __restrict__ res, float* __restrict__ C,
               int M, int N, int K) {
    __shared__ uint32_t As[2][BM][SST];
    __shared__ uint32_t Bs[2][BN][SST];

    const int bm = blockIdx.y * BM;
    const int bn = blockIdx.x * BN;
    const int tid  = threadIdx.x;
    const int warp = tid >> 5;
    const int lane = tid & 31;
    const int grp  = lane >> 2;   // 0..7
    const int tig  = lane & 3;    // 0..3
    const int wm = (warp >> 2) * 64;  // 0,64
    const int wn = (warp & 3) * 32;   // 0,32,64,96

    // global-load mapping: 2 float4 per thread per tile
    const int r0 = (tid) >> 2;              // row for i=0 slot: 0..63
    const int r1 = (tid + 256) >> 2;        // 64..127
    const int c4 = (tid & 3) * 4;

    float4 av[2], bv[2];
    float acc[4][4][4];
    #pragma unroll
    for (int i = 0; i < 4; i++)
        #pragma unroll
        for (int j = 0; j < 4; j++)
            #pragma unroll
            for (int r = 0; r < 4; r++) acc[i][j][r] = 0.0f;

    const int NT = K / BK;

    auto ldg = [&](int kt) {
        const float* ap = A + (size_t)(bm + r0) * K + kt * BK + c4;
        av[0] = *(const float4*)ap;
        av[1] = *(const float4*)(A + (size_t)(bm + r1) * K + kt * BK + c4);
        bv[0] = *(const float4*)(B + (size_t)(bn + r0) * K + kt * BK + c4);
        bv[1] = *(const float4*)(B + (size_t)(bn + r1) * K + kt * BK + c4);
    };
    auto sts = [&](int st) {
        uint4 u;
        u.x = f2tf32(av[0].x); u.y = f2tf32(av[0].y); u.z = f2tf32(av[0].z); u.w = f2tf32(av[0].w);
        *(uint4*)&As[st][r0][c4] = u;
        u.x = f2tf32(av[1].x); u.y = f2tf32(av[1].y); u.z = f2tf32(av[1].z); u.w = f2tf32(av[1].w);
        *(uint4*)&As[st][r1][c4] = u;
        u.x = f2tf32(bv[0].x); u.y = f2tf32(bv[0].y); u.z = f2tf32(bv[0].z); u.w = f2tf32(bv[0].w);
        *(uint4*)&Bs[st][r0][c4] = u;
        u.x = f2tf32(bv[1].x); u.y = f2tf32(bv[1].y); u.z = f2tf32(bv[1].z); u.w = f2tf32(bv[1].w);
        *(uint4*)&Bs[st][r1][c4] = u;
    };

    ldg(0);
    sts(0);
    __syncthreads();

    for (int kt = 0; kt < NT; kt++) {
        const int cur = kt & 1;
        if (kt + 1 < NT) ldg(kt + 1);

        #pragma unroll
        for (int ks = 0; ks < 2; ks++) {
            const int kb = ks * 8;
            uint32_t af[4][4], bf[4][2];
            #pragma unroll
            for (int mt = 0; mt < 4; mt++) {
                const int mr = wm + mt * 16;
                af[mt][0] = As[cur][mr + grp    ][kb + tig];
                af[mt][1] = As[cur][mr + grp + 8][kb + tig];
                af[mt][2] = As[cur][mr + grp    ][kb + tig + 4];
                af[mt][3] = As[cur][mr + grp + 8][kb + tig + 4];
            }
            #pragma unroll
            for (int nt = 0; nt < 4; nt++) {
                const int nr = wn + nt * 8 + grp;
                bf[nt][0] = Bs[cur][nr][kb + tig];
                bf[nt][1] = Bs[cur][nr][kb + tig + 4];
            }
            #pragma unroll
            for (int mt = 0; mt < 4; mt++)
                #pragma unroll
                for (int nt = 0; nt < 4; nt++) {
                    asm volatile(
                        "mma.sync.aligned.m16n8k8.row.col.f32.tf32.tf32.f32 "
                        "{%0,%1,%2,%3}, {%4,%5,%6,%7}, {%8,%9}, {%0,%1,%2,%3};\n"
                        : "+f"(acc[mt][nt][0]), "+f"(acc[mt][nt][1]),
                          "+f"(acc[mt][nt][2]), "+f"(acc[mt][nt][3])
                        : "r"(af[mt][0]), "r"(af[mt][1]), "r"(af[mt][2]), "r"(af[mt][3]),
                          "r"(bf[nt][0]), "r"(bf[nt][1]));
                }
        }

        if (kt + 1 < NT) sts((kt + 1) & 1);
        __syncthreads();
    }

    // epilogue
    #pragma unroll
    for (int mt = 0; mt < 4; mt++) {
        const int row = bm + wm + mt * 16 + grp;
        #pragma unroll
        for (int nt = 0; nt < 4; nt++) {
            const int col = bn + wn + nt * 8 + 2 * tig;
            size_t i0 = (size_t)row * N + col;
            size_t i1 = (size_t)(row + 8) * N + col;
            float2 v0 = make_float2(acc[mt][nt][0], acc[mt][nt][1]);
            float2 v1 = make_float2(acc[mt][nt][2], acc[mt][nt][3]);
            if (RESID) {
                float2 r0v = *(const float2*)&res[i0];
                float2 r1v = *(const float2*)&res[i1];
                v0.x += r0v.x; v0.y += r0v.y;
                v1.x += r1v.x; v1.y += r1v.y;
            }
            *(float2*)&C[i0] = v0;
            *(float2*)&C[i1] = v1;
        }
    }
}

// ---------------- RoPE on q and k in-place (table-driven) --------------------------
__global__ void rope_k(float* __restrict__ q, float* __restrict__ k,
                       const float* __restrict__ ct, const float* __restrict__ st) {
    int pos = blockIdx.x;
    int t = threadIdx.x;
    int h = t >> 5;
    int i = t & 31;
    float c = ct[pos * 32 + i];
    float s = st[pos * 32 + i];
    size_t base = (size_t)pos * DIM + h * HD + 2 * i;
    float2 qq = *(float2*)&q[base];
    float2 qo; qo.x = qq.x * c - qq.y * s; qo.y = qq.x * s + qq.y * c;
    *(float2*)&q[base] = qo;
    float2 kk = *(float2*)&k[base];
    float2 ko; ko.x = kk.x * c - kk.y * s; ko.y = kk.x * s + kk.y * c;
    *(float2*)&k[base] = ko;
}

// ---------------- Flash attention (non-causal), fp32 -------------------------------
#define AQ 128
#define AK 32

__global__ __launch_bounds__(128)
void flash_attn(const float* __restrict__ Q, const float* __restrict__ K,
                const float* __restrict__ V, float* __restrict__ O) {
    const int h  = blockIdx.y;
    const int q0 = blockIdx.x * AQ;
    const int t  = threadIdx.x;
    const float scale = 0.125f;   // 1/sqrt(64)

    __shared__ float Ks[AK][HD];
    __shared__ float Vs[AK][HD];

    float qreg[HD];
    float o[HD];
    float m = -1e30f, l = 0.0f;

    const float* qp = Q + (size_t)(q0 + t) * DIM + h * HD;
    #pragma unroll
    for (int d = 0; d < HD; d += 4) {
        float4 v4 = *(const float4*)(qp + d);
        qreg[d] = v4.x * scale; qreg[d + 1] = v4.y * scale;
        qreg[d + 2] = v4.z * scale; qreg[d + 3] = v4.w * scale;
        o[d] = 0.f; o[d + 1] = 0.f; o[d + 2] = 0.f; o[d + 3] = 0.f;
    }

    for (int k0 = 0; k0 < SEQ; k0 += AK) {
        __syncthreads();
        #pragma unroll
        for (int i = 0; i < 4; i++) {
            int idx = t + i * 128;            // 0..511 -> 32 rows x 16 float4
            int row = idx >> 4;
            int c   = (idx & 15) * 4;
            *(float4*)&Ks[row][c] = *(const float4*)&K[(size_t)(k0 + row) * DIM + h * HD + c];
            *(float4*)&Vs[row][c] = *(const float4*)&V[(size_t)(k0 + row) * DIM + h * HD + c];
        }
        __syncthreads();

        float s[AK];
        float tmax = -1e30f;
        #pragma unroll
        for (int j = 0; j < AK; j++) {
            float acc = 0.0f;
            #pragma unroll
            for (int d = 0; d < HD; d += 4) {
                float4 kv = *(const float4*)&Ks[j][d];
                acc = fmaf(qreg[d], kv.x, acc);
                acc = fmaf(qreg[d + 1], kv.y, acc);
                acc = fmaf(qreg[d + 2], kv.z, acc);
                acc = fmaf(qreg[d + 3], kv.w, acc);
            }
            s[j] = acc;
            tmax = fmaxf(tmax, acc);
        }

        float mnew = fmaxf(m, tmax);
        float corr = __expf(m - mnew);
        l *= corr;
        #pragma unroll
        for (int d = 0; d < HD; d++) o[d] *= corr;
        m = mnew;

        #pragma unroll
        for (int j = 0; j < AK; j++) {
            float p = __expf(s[j] - mnew);
            l += p;
            #pragma unroll
            for (int d = 0; d < HD; d += 4) {
                float4 vv = *(const float4*)&Vs[j][d];
                o[d]     = fmaf(p, vv.x, o[d]);
                o[d + 1] = fmaf(p, vv.y, o[d + 1]);
                o[d + 2] = fmaf(p, vv.z, o[d + 2]);
                o[d + 3] = fmaf(p, vv.w, o[d + 3]);
            }
        }
    }

    float invl = 1.0f / l;
    float* op = O + (size_t)(q0 + t) * DIM + h * HD;
    #pragma unroll
    for (int d = 0; d < HD; d += 4) {
        float4 v4;
        v4.x = o[d] * invl; v4.y = o[d + 1] * invl;
        v4.z = o[d + 2] * invl; v4.w = o[d + 3] * invl;
        *(float4*)(op + d) = v4;
    }
}

// ---------------- SwiGLU elementwise: a = silu(a) * b -------------------------------
__global__ void silu_mul_k(float* __restrict__ a, const float* __restrict__ b, int n4) {
    int i = blockIdx.x * blockDim.x + threadIdx.x;
    if (i < n4) {
        float4 x = ((float4*)a)[i];
        float4 y = ((const float4*)b)[i];
        x.x = x.x / (1.0f + __expf(-x.x)) * y.x;
        x.y = x.y / (1.0f + __expf(-x.y)) * y.y;
        x.z = x.z / (1.0f + __expf(-x.z)) * y.z;
        x.w = x.w / (1.0f + __expf(-x.w)) * y.w;
        ((float4*)a)[i] = x;
    }
}

// ---------------- launch -----------------------------------------------------------
extern "C" void kernel_launch(void* const* d_in, const int* in_sizes, int n_in,
                              void* d_out, int out_size) {
    const float* x  = (const float*)d_in[0];
    const float* wq = (const float*)d_in[1];
    const float* wk = (const float*)d_in[2];
    const float* wv = (const float*)d_in[3];
    const float* wo = (const float*)d_in[4];
    const float* w1 = (const float*)d_in[5];
    const float* w2 = (const float*)d_in[6];
    const float* w3 = (const float*)d_in[7];
    const float* ga = (const float*)d_in[8];
    const float* gf = (const float*)d_in[9];
    float* out = (float*)d_out;

    float *xn, *q, *k, *v, *at, *hn, *t1, *t3, *ct, *st;
    cudaGetSymbolAddress((void**)&xn, g_xn);
    cudaGetSymbolAddress((void**)&q,  g_q);
    cudaGetSymbolAddress((void**)&k,  g_k);
    cudaGetSymbolAddress((void**)&v,  g_v);
    cudaGetSymbolAddress((void**)&at, g_at);
    cudaGetSymbolAddress((void**)&hn, g_hn);
    cudaGetSymbolAddress((void**)&t1, g_t1);
    cudaGetSymbolAddress((void**)&t3, g_t3);
    cudaGetSymbolAddress((void**)&ct, g_cos);
    cudaGetSymbolAddress((void**)&st, g_sin);

    // 0) RoPE tables (double precision)
    rope_tables_k<<<(SEQ * 32) / 256, 256>>>(ct, st);

    // 1) attn RMSNorm
    rmsnorm_k<<<SEQ, 256>>>(x, ga, xn);

    // 2) QKV projections
    dim3 g1(DIM / BN, SEQ / BM);
    gemm_tf32<false><<<g1, 256>>>(xn, wq, nullptr, q, SEQ, DIM, DIM);
    gemm_tf32<false><<<g1, 256>>>(xn, wk, nullptr, k, SEQ, DIM, DIM);
    gemm_tf32<false><<<g1, 256>>>(xn, wv, nullptr, v, SEQ, DIM, DIM);

    // 3) RoPE on q, k
    rope_k<<<SEQ, 512>>>(q, k, ct, st);

    // 4) attention
    flash_attn<<<dim3(SEQ / AQ, NH), 128>>>(q, k, v, at);

    // 5) output projection + residual -> h (in d_out)
    gemm_tf32<true><<<g1, 256>>>(at, wo, x, out, SEQ, DIM, DIM);

    // 6) ffn RMSNorm
    rmsnorm_k<<<SEQ, 256>>>(out, gf, hn);

    // 7) w1 / w3 GEMMs
    dim3 g2(HIDDEN / BN, SEQ / BM);
    gemm_tf32<false><<<g2, 256>>>(hn, w1, nullptr, t1, SEQ, HIDDEN, DIM);
    gemm_tf32<false><<<g2, 256>>>(hn, w3, nullptr, t3, SEQ, HIDDEN, DIM);

    // 8) silu(t1) * t3 -> t1
    silu_mul_k<<<(SEQ * HIDDEN / 4 + 255) / 256, 256>>>(t1, t3, SEQ * HIDDEN / 4);

    // 9) down-projection + residual (in-place on d_out)
    gemm_tf32<true><<<g1, 256>>>(t1, w2, out, out, SEQ, DIM, HIDDEN);
}

// round 4
// speedup vs baseline: 3.2616x; 1.9587x over previous
#include <cuda_runtime.h>
#include <math.h>
#include <stdint.h>

#define SEQ    4096
#define DIM    1024
#define NH     16
#define HD     64
#define HIDDEN 4096

// ---------------- scratch -----------------------------------------------------------
__device__ float g_xn[SEQ * DIM];
__device__ float g_q [SEQ * DIM];
__device__ float g_k [SEQ * DIM];
__device__ float g_v [SEQ * DIM];
__device__ float g_at[SEQ * DIM];
__device__ float g_hn[SEQ * DIM];
__device__ float g_t1[SEQ * HIDDEN];
__device__ float g_t3[SEQ * HIDDEN];
__device__ float g_cos[SEQ * (HD / 2)];
__device__ float g_sin[SEQ * (HD / 2)];

__device__ __forceinline__ uint32_t f2tf32(float f) {
    uint32_t u;
    asm("cvt.rna.tf32.f32 %0, %1;" : "=r"(u) : "f"(f));
    return u;
}

__device__ __forceinline__ void mma_tf32(float* c, const uint32_t* a, uint32_t b0, uint32_t b1) {
    asm volatile(
        "mma.sync.aligned.m16n8k8.row.col.f32.tf32.tf32.f32 "
        "{%0,%1,%2,%3}, {%4,%5,%6,%7}, {%8,%9}, {%0,%1,%2,%3};\n"
        : "+f"(c[0]), "+f"(c[1]), "+f"(c[2]), "+f"(c[3])
        : "r"(a[0]), "r"(a[1]), "r"(a[2]), "r"(a[3]), "r"(b0), "r"(b1));
}

// ---------------- RoPE tables in double precision -----------------------------------
__global__ void rope_tables_k(float* __restrict__ c, float* __restrict__ s) {
    int idx = blockIdx.x * blockDim.x + threadIdx.x;   // SEQ*32
    int pos = idx >> 5;
    int i   = idx & 31;
    double inv = exp(-((double)(2 * i) / (double)HD) * log(10000.0));
    double ang = (double)pos * inv;
    double cs, sn;
    sincos(ang, &sn, &cs);
    c[idx] = (float)cs;
    s[idx] = (float)sn;
}

// ---------------- RMSNorm ------------------------------------------------------------
__global__ void rmsnorm_k(const float* __restrict__ x, const float* __restrict__ g,
                          float* __restrict__ o) {
    int row = blockIdx.x;
    const float4* xr = (const float4*)(x + (size_t)row * DIM);
    float4*       orow = (float4*)(o + (size_t)row * DIM);
    int t = threadIdx.x;                       // 256 threads
    float4 v = xr[t];
    float ss = v.x * v.x + v.y * v.y + v.z * v.z + v.w * v.w;
    #pragma unroll
    for (int off = 16; off; off >>= 1) ss += __shfl_xor_sync(0xffffffffu, ss, off);
    __shared__ float sp[8];
    if ((t & 31) == 0) sp[t >> 5] = ss;
    __syncthreads();
    if (t < 8) {
        float s2 = sp[t];
        #pragma unroll
        for (int off = 4; off; off >>= 1) s2 += __shfl_xor_sync(0xffu, s2, off);
        if (t == 0) sp[0] = s2;
    }
    __syncthreads();
    float rs = rsqrtf(sp[0] * (1.0f / DIM) + 1e-6f);
    float4 gg = ((const float4*)g)[t];
    float4 out;
    out.x = v.x * rs * gg.x;
    out.y = v.y * rs * gg.y;
    out.z = v.z * rs * gg.z;
    out.w = v.w * rs * gg.w;
    orow[t] = out;
}

// ---------------- tf32 tensor-core GEMM: C[M,N] = A[M,K] @ B[N,K]^T (+res) ----------
#define BM 128
#define BN 128
#define BK 16
#define SST 20

template <bool RESID>
__global__ __launch_bounds__(256, 2)
void gemm_tf32(const float* __restrict__ A, const float* __restrict__ B,
               const float* __restrict__ res, float* __restrict__ C,
               int M, int N, int K) {
    __shared__ uint32_t As[2][BM][SST];
    __shared__ uint32_t Bs[2][BN][SST];

    const int bm = blockIdx.y * BM;
    const int bn = blockIdx.x * BN;
    const int tid  = threadIdx.x;
    const int warp = tid >> 5;
    const int lane = tid & 31;
    const int grp  = lane >> 2;
    const int tig  = lane & 3;
    const int wm = (warp >> 2) * 64;
    const int wn = (warp & 3) * 32;

    const int r0 = (tid) >> 2;
    const int r1 = (tid + 256) >> 2;
    const int c4 = (tid & 3) * 4;

    float4 av[2], bv[2];
    float acc[4][4][4];
    #pragma unroll
    for (int i = 0; i < 4; i++)
        #pragma unroll
        for (int j = 0; j < 4; j++)
            #pragma unroll
            for (int r = 0; r < 4; r++) acc[i][j][r] = 0.0f;

    const int NT = K / BK;

    auto ldg = [&](int kt) {
        av[0] = *(const float4*)(A + (size_t)(bm + r0) * K + kt * BK + c4);
        av[1] = *(const float4*)(A + (size_t)(bm + r1) * K + kt * BK + c4);
        bv[0] = *(const float4*)(B + (size_t)(bn + r0) * K + kt * BK + c4);
        bv[1] = *(const float4*)(B + (size_t)(bn + r1) * K + kt * BK + c4);
    };
    auto sts = [&](int st) {
        uint4 u;
        u.x = f2tf32(av[0].x); u.y = f2tf32(av[0].y); u.z = f2tf32(av[0].z); u.w = f2tf32(av[0].w);
        *(uint4*)&As[st][r0][c4] = u;
        u.x = f2tf32(av[1].x); u.y = f2tf32(av[1].y); u.z = f2tf32(av[1].z); u.w = f2tf32(av[1].w);
        *(uint4*)&As[st][r1][c4] = u;
        u.x = f2tf32(bv[0].x); u.y = f2tf32(bv[0].y); u.z = f2tf32(bv[0].z); u.w = f2tf32(bv[0].w);
        *(uint4*)&Bs[st][r0][c4] = u;
        u.x = f2tf32(bv[1].x); u.y = f2tf32(bv[1].y); u.z = f2tf32(bv[1].z); u.w = f2tf32(bv[1].w);
        *(uint4*)&Bs[st][r1][c4] = u;
    };

    ldg(0);
    sts(0);
    __syncthreads();

    for (int kt = 0; kt < NT; kt++) {
        const int cur = kt & 1;
        if (kt + 1 < NT) ldg(kt + 1);

        #pragma unroll
        for (int ks = 0; ks < 2; ks++) {
            const int kb = ks * 8;
            uint32_t af[4][4], bf[4][2];
            #pragma unroll
            for (int mt = 0; mt < 4; mt++) {
                const int mr = wm + mt * 16;
                af[mt][0] = As[cur][mr + grp    ][kb + tig];
                af[mt][1] = As[cur][mr + grp + 8][kb + tig];
                af[mt][2] = As[cur][mr + grp    ][kb + tig + 4];
                af[mt][3] = As[cur][mr + grp + 8][kb + tig + 4];
            }
            #pragma unroll
            for (int nt = 0; nt < 4; nt++) {
                const int nr = wn + nt * 8 + grp;
                bf[nt][0] = Bs[cur][nr][kb + tig];
                bf[nt][1] = Bs[cur][nr][kb + tig + 4];
            }
            #pragma unroll
            for (int mt = 0; mt < 4; mt++)
                #pragma unroll
                for (int nt = 0; nt < 4; nt++)
                    mma_tf32(acc[mt][nt], af[mt], bf[nt][0], bf[nt][1]);
        }

        if (kt + 1 < NT) sts((kt + 1) & 1);
        __syncthreads();
    }

    #pragma unroll
    for (int mt = 0; mt < 4; mt++) {
        const int row = bm + wm + mt * 16 + grp;
        #pragma unroll
        for (int nt = 0; nt < 4; nt++) {
            const int col = bn + wn + nt * 8 + 2 * tig;
            size_t i0 = (size_t)row * N + col;
            size_t i1 = (size_t)(row + 8) * N + col;
            float2 v0 = make_float2(acc[mt][nt][0], acc[mt][nt][1]);
            float2 v1 = make_float2(acc[mt][nt][2], acc[mt][nt][3]);
            if (RESID) {
                float2 r0v = *(const float2*)&res[i0];
                float2 r1v = *(const float2*)&res[i1];
                v0.x += r0v.x; v0.y += r0v.y;
                v1.x += r1v.x; v1.y += r1v.y;
            }
            *(float2*)&C[i0] = v0;
            *(float2*)&C[i1] = v1;
        }
    }
}

// ---------------- RoPE ---------------------------------------------------------------
__global__ void rope_k(float* __restrict__ q, float* __restrict__ k,
                       const float* __restrict__ ct, const float* __restrict__ st) {
    int pos = blockIdx.x;
    int t = threadIdx.x;
    int h = t >> 5;
    int i = t & 31;
    float c = ct[pos * 32 + i];
    float s = st[pos * 32 + i];
    size_t base = (size_t)pos * DIM + h * HD + 2 * i;
    float2 qq = *(float2*)&q[base];
    float2 qo; qo.x = qq.x * c - qq.y * s; qo.y = qq.x * s + qq.y * c;
    *(float2*)&q[base] = qo;
    float2 kk = *(float2*)&k[base];
    float2 ko; ko.x = kk.x * c - kk.y * s; ko.y = kk.x * s + kk.y * c;
    *(float2*)&k[base] = ko;
}

// ---------------- Tensor-core flash attention (tf32, non-causal) --------------------
// Block: one head, 64 query rows, 4 warps (16 rows each). KV tiles of 64.
// Ks/Ps stride 68 (= 4 mod 32) and Vs stride 72 (= 8 mod 32): conflict-free frags.
#define BQ   64
#define BKV  64
#define KP   68
#define VP   72

__global__ __launch_bounds__(128, 3)
void flash_attn_tc(const float* __restrict__ Q, const float* __restrict__ K,
                   const float* __restrict__ V, float* __restrict__ O) {
    __shared__ uint32_t Ks[BKV][KP];
    __shared__ uint32_t Vs[BKV][VP];
    __shared__ uint32_t Ps[BQ][KP];

    const int h  = blockIdx.y;
    const int q0 = blockIdx.x * BQ;
    const int tid  = threadIdx.x;
    const int warp = tid >> 5;
    const int lane = tid & 31;
    const int grp  = lane >> 2;   // 0..7
    const int tig  = lane & 3;    // 0..3
    const int wm   = warp * 16;

    // Q fragments (scaled by 1/sqrt(64), tf32)
    uint32_t qf[8][4];
    {
        const float* qb = Q + (size_t)(q0 + wm) * DIM + h * HD;
        #pragma unroll
        for (int ks = 0; ks < 8; ks++) {
            qf[ks][0] = f2tf32(0.125f * qb[(size_t)grp       * DIM + ks * 8 + tig]);
            qf[ks][1] = f2tf32(0.125f * qb[(size_t)(grp + 8) * DIM + ks * 8 + tig]);
            qf[ks][2] = f2tf32(0.125f * qb[(size_t)grp       * DIM + ks * 8 + tig + 4]);
            qf[ks][3] = f2tf32(0.125f * qb[(size_t)(grp + 8) * DIM + ks * 8 + tig + 4]);
        }
    }

    float o[8][4];
    #pragma unroll
    for (int dt = 0; dt < 8; dt++)
        #pragma unroll
        for (int r = 0; r < 4; r++) o[dt][r] = 0.0f;
    float m0 = -1e30f, m1 = -1e30f, l0 = 0.0f, l1 = 0.0f;

    for (int k0 = 0; k0 < SEQ; k0 += BKV) {
        __syncthreads();
        // load K, V tiles (tf32)
        #pragma unroll
        for (int i = 0; i < 8; i++) {
            int idx = tid + i * 128;          // 1024 float4 slots over 64x64
            int row = idx >> 4;
            int c   = (idx & 15) * 4;
            float4 k4 = *(const float4*)&K[(size_t)(k0 + row) * DIM + h * HD + c];
            Ks[row][c + 0] = f2tf32(k4.x); Ks[row][c + 1] = f2tf32(k4.y);
            Ks[row][c + 2] = f2tf32(k4.z); Ks[row][c + 3] = f2tf32(k4.w);
            float4 v4 = *(const float4*)&V[(size_t)(k0 + row) * DIM + h * HD + c];
            Vs[row][c + 0] = f2tf32(v4.x); Vs[row][c + 1] = f2tf32(v4.y);
            Vs[row][c + 2] = f2tf32(v4.z); Vs[row][c + 3] = f2tf32(v4.w);
        }
        __syncthreads();

        // S = Q K^T  (16 x 64 per warp)
        float sc[8][4];
        #pragma unroll
        for (int nt = 0; nt < 8; nt++)
            #pragma unroll
            for (int r = 0; r < 4; r++) sc[nt][r] = 0.0f;
        #pragma unroll
        for (int ks = 0; ks < 8; ks++) {
            const int kb = ks * 8;
            #pragma unroll
            for (int nt = 0; nt < 8; nt++) {
                uint32_t b0 = Ks[nt * 8 + grp][kb + tig];
                uint32_t b1 = Ks[nt * 8 + grp][kb + tig + 4];
                mma_tf32(sc[nt], qf[ks], b0, b1);
            }
        }

        // online softmax (rows grp and grp+8 of this warp's 16)
        float mx0 = -1e30f, mx1 = -1e30f;
        #pragma unroll
        for (int nt = 0; nt < 8; nt++) {
            mx0 = fmaxf(mx0, fmaxf(sc[nt][0], sc[nt][1]));
            mx1 = fmaxf(mx1, fmaxf(sc[nt][2], sc[nt][3]));
        }
        mx0 = fmaxf(mx0, __shfl_xor_sync(0xffffffffu, mx0, 1));
        mx0 = fmaxf(mx0, __shfl_xor_sync(0xffffffffu, mx0, 2));
        mx1 = fmaxf(mx1, __shfl_xor_sync(0xffffffffu, mx1, 1));
        mx1 = fmaxf(mx1, __shfl_xor_sync(0xffffffffu, mx1, 2));

        float mn0 = fmaxf(m0, mx0);
        float mn1 = fmaxf(m1, mx1);
        float cr0 = __expf(m0 - mn0);
        float cr1 = __expf(m1 - mn1);
        m0 = mn0; m1 = mn1;

        float s0 = 0.0f, s1 = 0.0f;
        #pragma unroll
        for (int nt = 0; nt < 8; nt++) {
            sc[nt][0] = __expf(sc[nt][0] - mn0);
            sc[nt][1] = __expf(sc[nt][1] - mn0);
            sc[nt][2] = __expf(sc[nt][2] - mn1);
            sc[nt][3] = __expf(sc[nt][3] - mn1);
            s0 += sc[nt][0] + sc[nt][1];
            s1 += sc[nt][2] + sc[nt][3];
        }
        s0 += __shfl_xor_sync(0xffffffffu, s0, 1);
        s0 += __shfl_xor_sync(0xffffffffu, s0, 2);
        s1 += __shfl_xor_sync(0xffffffffu, s1, 1);
        s1 += __shfl_xor_sync(0xffffffffu, s1, 2);
        l0 = l0 * cr0 + s0;
        l1 = l1 * cr1 + s1;

        #pragma unroll
        for (int dt = 0; dt < 8; dt++) {
            o[dt][0] *= cr0; o[dt][1] *= cr0;
            o[dt][2] *= cr1; o[dt][3] *= cr1;
        }

        // P -> smem (tf32), per-warp private rows
        #pragma unroll
        for (int nt = 0; nt < 8; nt++) {
            uint2 u0 = make_uint2(f2tf32(sc[nt][0]), f2tf32(sc[nt][1]));
            uint2 u1 = make_uint2(f2tf32(sc[nt][2]), f2tf32(sc[nt][3]));
            *(uint2*)&Ps[wm + grp    ][nt * 8 + 2 * tig] = u0;
            *(uint2*)&Ps[wm + grp + 8][nt * 8 + 2 * tig] = u1;
        }
        __syncwarp();

        // O += P V
        #pragma unroll
        for (int ks = 0; ks < 8; ks++) {
            const int kb = ks * 8;
            uint32_t pa[4];
            pa[0] = Ps[wm + grp    ][kb + tig];
            pa[1] = Ps[wm + grp + 8][kb + tig];
            pa[2] = Ps[wm + grp    ][kb + tig + 4];
            pa[3] = Ps[wm + grp + 8][kb + tig + 4];
            #pragma unroll
            for (int dt = 0; dt < 8; dt++) {
                uint32_t b0 = Vs[kb + tig    ][dt * 8 + grp];
                uint32_t b1 = Vs[kb + tig + 4][dt * 8 + grp];
                mma_tf32(o[dt], pa, b0, b1);
            }
        }
        __syncwarp();
    }

    float il0 = 1.0f / l0;
    float il1 = 1.0f / l1;
    #pragma unroll
    for (int dt = 0; dt < 8; dt++) {
        size_t i0 = (size_t)(q0 + wm + grp    ) * DIM + h * HD + dt * 8 + 2 * tig;
        size_t i1 = (size_t)(q0 + wm + grp + 8) * DIM + h * HD + dt * 8 + 2 * tig;
        *(float2*)&O[i0] = make_float2(o[dt][0] * il0, o[dt][1] * il0);
        *(float2*)&O[i1] = make_float2(o[dt][2] * il1, o[dt][3] * il1);
    }
}

// ---------------- SwiGLU elementwise -------------------------------------------------
__global__ void silu_mul_k(float* __restrict__ a, const float* __restrict__ b, int n4) {
    int i = blockIdx.x * blockDim.x + threadIdx.x;
    if (i < n4) {
        float4 x = ((float4*)a)[i];
        float4 y = ((const float4*)b)[i];
        x.x = x.x / (1.0f + __expf(-x.x)) * y.x;
        x.y = x.y / (1.0f + __expf(-x.y)) * y.y;
        x.z = x.z / (1.0f + __expf(-x.z)) * y.z;
        x.w = x.w / (1.0f + __expf(-x.w)) * y.w;
        ((float4*)a)[i] = x;
    }
}

// ---------------- launch --------------------------------------------------------------
extern "C" void kernel_launch(void* const* d_in, const int* in_sizes, int n_in,
                              void* d_out, int out_size) {
    const float* x  = (const float*)d_in[0];
    const float* wq = (const float*)d_in[1];
    const float* wk = (const float*)d_in[2];
    const float* wv = (const float*)d_in[3];
    const float* wo = (const float*)d_in[4];
    const float* w1 = (const float*)d_in[5];
    const float* w2 = (const float*)d_in[6];
    const float* w3 = (const float*)d_in[7];
    const float* ga = (const float*)d_in[8];
    const float* gf = (const float*)d_in[9];
    float* out = (float*)d_out;

    float *xn, *q, *k, *v, *at, *hn, *t1, *t3, *ct, *st;
    cudaGetSymbolAddress((void**)&xn, g_xn);
    cudaGetSymbolAddress((void**)&q,  g_q);
    cudaGetSymbolAddress((void**)&k,  g_k);
    cudaGetSymbolAddress((void**)&v,  g_v);
    cudaGetSymbolAddress((void**)&at, g_at);
    cudaGetSymbolAddress((void**)&hn, g_hn);
    cudaGetSymbolAddress((void**)&t1, g_t1);
    cudaGetSymbolAddress((void**)&t3, g_t3);
    cudaGetSymbolAddress((void**)&ct, g_cos);
    cudaGetSymbolAddress((void**)&st, g_sin);

    rope_tables_k<<<(SEQ * 32) / 256, 256>>>(ct, st);
    rmsnorm_k<<<SEQ, 256>>>(x, ga, xn);

    dim3 g1(DIM / BN, SEQ / BM);
    gemm_tf32<false><<<g1, 256>>>(xn, wq, nullptr, q, SEQ, DIM, DIM);
    gemm_tf32<false><<<g1, 256>>>(xn, wk, nullptr, k, SEQ, DIM, DIM);
    gemm_tf32<false><<<g1, 256>>>(xn, wv, nullptr, v, SEQ, DIM, DIM);

    rope_k<<<SEQ, 512>>>(q, k, ct, st);

    flash_attn_tc<<<dim3(SEQ / BQ, NH), 128>>>(q, k, v, at);

    gemm_tf32<true><<<g1, 256>>>(at, wo, x, out, SEQ, DIM, DIM);
    rmsnorm_k<<<SEQ, 256>>>(out, gf, hn);

    dim3 g2(HIDDEN / BN, SEQ / BM);
    gemm_tf32<false><<<g2, 256>>>(hn, w1, nullptr, t1, SEQ, HIDDEN, DIM);
    gemm_tf32<false><<<g2, 256>>>(hn, w3, nullptr, t3, SEQ, HIDDEN, DIM);

    silu_mul_k<<<(SEQ * HIDDEN / 4 + 255) / 256, 256>>>(t1, t3, SEQ * HIDDEN / 4);

    gemm_tf32<true><<<g1, 256>>>(t1, w2, out, out, SEQ, DIM, HIDDEN);
}

// round 5
// speedup vs baseline: 3.5763x; 1.0965x over previous
#include <cuda_runtime.h>
#include <math.h>
#include <stdint.h>

#define SEQ    4096
#define DIM    1024
#define NH     16
#define HD     64
#define HIDDEN 4096

// ---------------- scratch -----------------------------------------------------------
__device__ float g_xn[SEQ * DIM];
__device__ float g_q [SEQ * DIM];
__device__ float g_k [SEQ * DIM];
__device__ float g_v [SEQ * DIM];
__device__ float g_at[SEQ * DIM];
__device__ float g_hn[SEQ * DIM];
__device__ float g_t1[SEQ * HIDDEN];
__device__ float g_t3[SEQ * HIDDEN];
__device__ float g_cos[SEQ * (HD / 2)];
__device__ float g_sin[SEQ * (HD / 2)];
__device__ float g_wt[16777216];          // tf32-rounded weights (64MB)

#define WQO 0
#define WKO 1048576
#define WVO 2097152
#define WOO 3145728
#define W1O 4194304
#define W3O 8388608
#define W2O 12582912

__device__ __forceinline__ uint32_t f2tf32(float f) {
    uint32_t u;
    asm("cvt.rna.tf32.f32 %0, %1;" : "=r"(u) : "f"(f));
    return u;
}
__device__ __forceinline__ float rtf32(float f) { return __uint_as_float(f2tf32(f)); }

__device__ __forceinline__ void mma_tf32(float* c, const uint32_t* a, uint32_t b0, uint32_t b1) {
    asm volatile(
        "mma.sync.aligned.m16n8k8.row.col.f32.tf32.tf32.f32 "
        "{%0,%1,%2,%3}, {%4,%5,%6,%7}, {%8,%9}, {%0,%1,%2,%3};\n"
        : "+f"(c[0]), "+f"(c[1]), "+f"(c[2]), "+f"(c[3])
        : "r"(a[0]), "r"(a[1]), "r"(a[2]), "r"(a[3]), "r"(b0), "r"(b1));
}

__device__ __forceinline__ void cp16(uint32_t saddr, const void* gptr) {
    asm volatile("cp.async.cg.shared.global [%0], [%1], 16;" :: "r"(saddr), "l"(gptr));
}

// ---------------- weight tf32 pre-round ----------------------------------------------
__global__ void cvt_w_k(const float* __restrict__ src, float* __restrict__ dst, int n4) {
    int stride = gridDim.x * blockDim.x;
    for (int i = blockIdx.x * blockDim.x + threadIdx.x; i < n4; i += stride) {
        float4 v = ((const float4*)src)[i];
        v.x = rtf32(v.x); v.y = rtf32(v.y); v.z = rtf32(v.z); v.w = rtf32(v.w);
        ((float4*)dst)[i] = v;
    }
}

// ---------------- RoPE tables in double precision ------------------------------------
__global__ void rope_tables_k(float* __restrict__ c, float* __restrict__ s) {
    int idx = blockIdx.x * blockDim.x + threadIdx.x;   // SEQ*32
    int pos = idx >> 5;
    int i   = idx & 31;
    double inv = exp(-((double)(2 * i) / (double)HD) * log(10000.0));
    double ang = (double)pos * inv;
    double cs, sn;
    sincos(ang, &sn, &cs);
    c[idx] = (float)cs;
    s[idx] = (float)sn;
}

// ---------------- RMSNorm (output tf32-rounded: it feeds GEMM A operand) -------------
__global__ void rmsnorm_k(const float* __restrict__ x, const float* __restrict__ g,
                          float* __restrict__ o) {
    int row = blockIdx.x;
    const float4* xr = (const float4*)(x + (size_t)row * DIM);
    float4*       orow = (float4*)(o + (size_t)row * DIM);
    int t = threadIdx.x;                       // 256 threads
    float4 v = xr[t];
    float ss = v.x * v.x + v.y * v.y + v.z * v.z + v.w * v.w;
    #pragma unroll
    for (int off = 16; off; off >>= 1) ss += __shfl_xor_sync(0xffffffffu, ss, off);
    __shared__ float sp[8];
    if ((t & 31) == 0) sp[t >> 5] = ss;
    __syncthreads();
    if (t < 8) {
        float s2 = sp[t];
        #pragma unroll
        for (int off = 4; off; off >>= 1) s2 += __shfl_xor_sync(0xffu, s2, off);
        if (t == 0) sp[0] = s2;
    }
    __syncthreads();
    float rs = rsqrtf(sp[0] * (1.0f / DIM) + 1e-6f);
    float4 gg = ((const float4*)g)[t];
    float4 out;
    out.x = rtf32(v.x * rs * gg.x);
    out.y = rtf32(v.y * rs * gg.y);
    out.z = rtf32(v.z * rs * gg.z);
    out.w = rtf32(v.w * rs * gg.w);
    orow[t] = out;
}

// ---------------- tf32 GEMM, cp.async 3-stage, batched over blockIdx.z ---------------
// C[M,N] = A[M,K] @ B[N,K]^T (+res).  Inputs already tf32-rounded fp32 bits.
#define BM 128
#define BN 128
#define BK 16
#define SST 20
#define STAGES 3

struct Batch3 {
    const float* B[3];
    float*       C[3];
    const float* R[3];
};

template <bool RESID>
__global__ __launch_bounds__(256, 2)
void gemm_tc(const float* __restrict__ A, Batch3 bt, int M, int N, int K) {
    const float* __restrict__ Bp = bt.B[blockIdx.z];
    float*       __restrict__ Cp = bt.C[blockIdx.z];
    const float* __restrict__ Rp = bt.R[blockIdx.z];

    __shared__ uint32_t As[STAGES][BM][SST];
    __shared__ uint32_t Bs[STAGES][BN][SST];

    const int bm = blockIdx.y * BM;
    const int bn = blockIdx.x * BN;
    const int tid  = threadIdx.x;
    const int warp = tid >> 5;
    const int lane = tid & 31;
    const int grp  = lane >> 2;
    const int tig  = lane & 3;
    const int wm = (warp >> 2) * 64;
    const int wn = (warp & 3) * 32;

    const int r0 = tid >> 2;          // 0..63
    const int r1 = r0 + 64;           // 64..127
    const int c4 = (tid & 3) * 4;

    float acc[4][4][4];
    #pragma unroll
    for (int i = 0; i < 4; i++)
        #pragma unroll
        for (int j = 0; j < 4; j++)
            #pragma unroll
            for (int r = 0; r < 4; r++) acc[i][j][r] = 0.0f;

    const int NT = K / BK;

    auto issue = [&](int kt) {
        const int st = kt % STAGES;
        cp16((uint32_t)__cvta_generic_to_shared(&As[st][r0][c4]),
             A + (size_t)(bm + r0) * K + kt * BK + c4);
        cp16((uint32_t)__cvta_generic_to_shared(&As[st][r1][c4]),
             A + (size_t)(bm + r1) * K + kt * BK + c4);
        cp16((uint32_t)__cvta_generic_to_shared(&Bs[st][r0][c4]),
             Bp + (size_t)(bn + r0) * K + kt * BK + c4);
        cp16((uint32_t)__cvta_generic_to_shared(&Bs[st][r1][c4]),
             Bp + (size_t)(bn + r1) * K + kt * BK + c4);
        asm volatile("cp.async.commit_group;");
    };

    issue(0);
    issue(1);

    for (int kt = 0; kt < NT; kt++) {
        if (kt + 1 < NT) {
            asm volatile("cp.async.wait_group 1;");
        } else {
            asm volatile("cp.async.wait_group 0;");
        }
        __syncthreads();
        if (kt + 2 < NT) issue(kt + 2);

        const int cur = kt % STAGES;
        #pragma unroll
        for (int ks = 0; ks < 2; ks++) {
            const int kb = ks * 8;
            uint32_t af[4][4], bf[4][2];
            #pragma unroll
            for (int mt = 0; mt < 4; mt++) {
                const int mr = wm + mt * 16;
                af[mt][0] = As[cur][mr + grp    ][kb + tig];
                af[mt][1] = As[cur][mr + grp + 8][kb + tig];
                af[mt][2] = As[cur][mr + grp    ][kb + tig + 4];
                af[mt][3] = As[cur][mr + grp + 8][kb + tig + 4];
            }
            #pragma unroll
            for (int nt = 0; nt < 4; nt++) {
                const int nr = wn + nt * 8 + grp;
                bf[nt][0] = Bs[cur][nr][kb + tig];
                bf[nt][1] = Bs[cur][nr][kb + tig + 4];
            }
            #pragma unroll
            for (int mt = 0; mt < 4; mt++)
                #pragma unroll
                for (int nt = 0; nt < 4; nt++)
                    mma_tf32(acc[mt][nt], af[mt], bf[nt][0], bf[nt][1]);
        }
    }

    #pragma unroll
    for (int mt = 0; mt < 4; mt++) {
        const int row = bm + wm + mt * 16 + grp;
        #pragma unroll
        for (int nt = 0; nt < 4; nt++) {
            const int col = bn + wn + nt * 8 + 2 * tig;
            size_t i0 = (size_t)row * N + col;
            size_t i1 = (size_t)(row + 8) * N + col;
            float2 v0 = make_float2(acc[mt][nt][0], acc[mt][nt][1]);
            float2 v1 = make_float2(acc[mt][nt][2], acc[mt][nt][3]);
            if (RESID) {
                float2 r0v = *(const float2*)&Rp[i0];
                float2 r1v = *(const float2*)&Rp[i1];
                v0.x += r0v.x; v0.y += r0v.y;
                v1.x += r1v.x; v1.y += r1v.y;
            }
            *(float2*)&Cp[i0] = v0;
            *(float2*)&Cp[i1] = v1;
        }
    }
}

// ---------------- RoPE ---------------------------------------------------------------
__global__ void rope_k(float* __restrict__ q, float* __restrict__ k,
                       const float* __restrict__ ct, const float* __restrict__ st) {
    int pos = blockIdx.x;
    int t = threadIdx.x;
    int h = t >> 5;
    int i = t & 31;
    float c = ct[pos * 32 + i];
    float s = st[pos * 32 + i];
    size_t base = (size_t)pos * DIM + h * HD + 2 * i;
    float2 qq = *(float2*)&q[base];
    float2 qo; qo.x = qq.x * c - qq.y * s; qo.y = qq.x * s + qq.y * c;
    *(float2*)&q[base] = qo;
    float2 kk = *(float2*)&k[base];
    float2 ko; ko.x = kk.x * c - kk.y * s; ko.y = kk.x * s + kk.y * c;
    *(float2*)&k[base] = ko;
}

// ---------------- Tensor-core flash attention (tf32, non-causal) ---------------------
#define BQ   64
#define BKV  64
#define KP   68
#define VP   72

__global__ __launch_bounds__(128, 3)
void flash_attn_tc(const float* __restrict__ Q, const float* __restrict__ K,
                   const float* __restrict__ V, float* __restrict__ O) {
    __shared__ uint32_t Ks[BKV][KP];
    __shared__ uint32_t Vs[BKV][VP];
    __shared__ uint32_t Ps[BQ][KP];

    const int h  = blockIdx.y;
    const int q0 = blockIdx.x * BQ;
    const int tid  = threadIdx.x;
    const int warp = tid >> 5;
    const int lane = tid & 31;
    const int grp  = lane >> 2;
    const int tig  = lane & 3;
    const int wm   = warp * 16;

    uint32_t qf[8][4];
    {
        const float* qb = Q + (size_t)(q0 + wm) * DIM + h * HD;
        #pragma unroll
        for (int ks = 0; ks < 8; ks++) {
            qf[ks][0] = f2tf32(0.125f * qb[(size_t)grp       * DIM + ks * 8 + tig]);
            qf[ks][1] = f2tf32(0.125f * qb[(size_t)(grp + 8) * DIM + ks * 8 + tig]);
            qf[ks][2] = f2tf32(0.125f * qb[(size_t)grp       * DIM + ks * 8 + tig + 4]);
            qf[ks][3] = f2tf32(0.125f * qb[(size_t)(grp + 8) * DIM + ks * 8 + tig + 4]);
        }
    }

    float o[8][4];
    #pragma unroll
    for (int dt = 0; dt < 8; dt++)
        #pragma unroll
        for (int r = 0; r < 4; r++) o[dt][r] = 0.0f;
    float m0 = -1e30f, m1 = -1e30f, l0 = 0.0f, l1 = 0.0f;

    for (int k0 = 0; k0 < SEQ; k0 += BKV) {
        __syncthreads();
        #pragma unroll
        for (int i = 0; i < 8; i++) {
            int idx = tid + i * 128;
            int row = idx >> 4;
            int c   = (idx & 15) * 4;
            float4 k4 = *(const float4*)&K[(size_t)(k0 + row) * DIM + h * HD + c];
            Ks[row][c + 0] = f2tf32(k4.x); Ks[row][c + 1] = f2tf32(k4.y);
            Ks[row][c + 2] = f2tf32(k4.z); Ks[row][c + 3] = f2tf32(k4.w);
            float4 v4 = *(const float4*)&V[(size_t)(k0 + row) * DIM + h * HD + c];
            Vs[row][c + 0] = f2tf32(v4.x); Vs[row][c + 1] = f2tf32(v4.y);
            Vs[row][c + 2] = f2tf32(v4.z); Vs[row][c + 3] = f2tf32(v4.w);
        }
        __syncthreads();

        float sc[8][4];
        #pragma unroll
        for (int nt = 0; nt < 8; nt++)
            #pragma unroll
            for (int r = 0; r < 4; r++) sc[nt][r] = 0.0f;
        #pragma unroll
        for (int ks = 0; ks < 8; ks++) {
            const int kb = ks * 8;
            #pragma unroll
            for (int nt = 0; nt < 8; nt++) {
                uint32_t b0 = Ks[nt * 8 + grp][kb + tig];
                uint32_t b1 = Ks[nt * 8 + grp][kb + tig + 4];
                mma_tf32(sc[nt], qf[ks], b0, b1);
            }
        }

        float mx0 = -1e30f, mx1 = -1e30f;
        #pragma unroll
        for (int nt = 0; nt < 8; nt++) {
            mx0 = fmaxf(mx0, fmaxf(sc[nt][0], sc[nt][1]));
            mx1 = fmaxf(mx1, fmaxf(sc[nt][2], sc[nt][3]));
        }
        mx0 = fmaxf(mx0, __shfl_xor_sync(0xffffffffu, mx0, 1));
        mx0 = fmaxf(mx0, __shfl_xor_sync(0xffffffffu, mx0, 2));
        mx1 = fmaxf(mx1, __shfl_xor_sync(0xffffffffu, mx1, 1));
        mx1 = fmaxf(mx1, __shfl_xor_sync(0xffffffffu, mx1, 2));

        float mn0 = fmaxf(m0, mx0);
        float mn1 = fmaxf(m1, mx1);
        float cr0 = __expf(m0 - mn0);
        float cr1 = __expf(m1 - mn1);
        m0 = mn0; m1 = mn1;

        float s0 = 0.0f, s1 = 0.0f;
        #pragma unroll
        for (int nt = 0; nt < 8; nt++) {
            sc[nt][0] = __expf(sc[nt][0] - mn0);
            sc[nt][1] = __expf(sc[nt][1] - mn0);
            sc[nt][2] = __expf(sc[nt][2] - mn1);
            sc[nt][3] = __expf(sc[nt][3] - mn1);
            s0 += sc[nt][0] + sc[nt][1];
            s1 += sc[nt][2] + sc[nt][3];
        }
        s0 += __shfl_xor_sync(0xffffffffu, s0, 1);
        s0 += __shfl_xor_sync(0xffffffffu, s0, 2);
        s1 += __shfl_xor_sync(0xffffffffu, s1, 1);
        s1 += __shfl_xor_sync(0xffffffffu, s1, 2);
        l0 = l0 * cr0 + s0;
        l1 = l1 * cr1 + s1;

        #pragma unroll
        for (int dt = 0; dt < 8; dt++) {
            o[dt][0] *= cr0; o[dt][1] *= cr0;
            o[dt][2] *= cr1; o[dt][3] *= cr1;
        }

        #pragma unroll
        for (int nt = 0; nt < 8; nt++) {
            uint2 u0 = make_uint2(f2tf32(sc[nt][0]), f2tf32(sc[nt][1]));
            uint2 u1 = make_uint2(f2tf32(sc[nt][2]), f2tf32(sc[nt][3]));
            *(uint2*)&Ps[wm + grp    ][nt * 8 + 2 * tig] = u0;
            *(uint2*)&Ps[wm + grp + 8][nt * 8 + 2 * tig] = u1;
        }
        __syncwarp();

        #pragma unroll
        for (int ks = 0; ks < 8; ks++) {
            const int kb = ks * 8;
            uint32_t pa[4];
            pa[0] = Ps[wm + grp    ][kb + tig];
            pa[1] = Ps[wm + grp + 8][kb + tig];
            pa[2] = Ps[wm + grp    ][kb + tig + 4];
            pa[3] = Ps[wm + grp + 8][kb + tig + 4];
            #pragma unroll
            for (int dt = 0; dt < 8; dt++) {
                uint32_t b0 = Vs[kb + tig    ][dt * 8 + grp];
                uint32_t b1 = Vs[kb + tig + 4][dt * 8 + grp];
                mma_tf32(o[dt], pa, b0, b1);
            }
        }
        __syncwarp();
    }

    // output tf32-rounded: feeds Wo GEMM as A operand
    float il0 = 1.0f / l0;
    float il1 = 1.0f / l1;
    #pragma unroll
    for (int dt = 0; dt < 8; dt++) {
        size_t i0 = (size_t)(q0 + wm + grp    ) * DIM + h * HD + dt * 8 + 2 * tig;
        size_t i1 = (size_t)(q0 + wm + grp + 8) * DIM + h * HD + dt * 8 + 2 * tig;
        *(float2*)&O[i0] = make_float2(rtf32(o[dt][0] * il0), rtf32(o[dt][1] * il0));
        *(float2*)&O[i1] = make_float2(rtf32(o[dt][2] * il1), rtf32(o[dt][3] * il1));
    }
}

// ---------------- SwiGLU elementwise (output tf32-rounded: feeds W2 GEMM) ------------
__global__ void silu_mul_k(float* __restrict__ a, const float* __restrict__ b, int n4) {
    int i = blockIdx.x * blockDim.x + threadIdx.x;
    if (i < n4) {
        float4 x = ((float4*)a)[i];
        float4 y = ((const float4*)b)[i];
        x.x = rtf32(x.x / (1.0f + __expf(-x.x)) * y.x);
        x.y = rtf32(x.y / (1.0f + __expf(-x.y)) * y.y);
        x.z = rtf32(x.z / (1.0f + __expf(-x.z)) * y.z);
        x.w = rtf32(x.w / (1.0f + __expf(-x.w)) * y.w);
        ((float4*)a)[i] = x;
    }
}

// ---------------- launch --------------------------------------------------------------
extern "C" void kernel_launch(void* const* d_in, const int* in_sizes, int n_in,
                              void* d_out, int out_size) {
    const float* x  = (const float*)d_in[0];
    const float* wq = (const float*)d_in[1];
    const float* wk = (const float*)d_in[2];
    const float* wv = (const float*)d_in[3];
    const float* wo = (const float*)d_in[4];
    const float* w1 = (const float*)d_in[5];
    const float* w2 = (const float*)d_in[6];
    const float* w3 = (const float*)d_in[7];
    const float* ga = (const float*)d_in[8];
    const float* gf = (const float*)d_in[9];
    float* out = (float*)d_out;

    float *xn, *q, *k, *v, *at, *hn, *t1, *t3, *ct, *st, *wt;
    cudaGetSymbolAddress((void**)&xn, g_xn);
    cudaGetSymbolAddress((void**)&q,  g_q);
    cudaGetSymbolAddress((void**)&k,  g_k);
    cudaGetSymbolAddress((void**)&v,  g_v);
    cudaGetSymbolAddress((void**)&at, g_at);
    cudaGetSymbolAddress((void**)&hn, g_hn);
    cudaGetSymbolAddress((void**)&t1, g_t1);
    cudaGetSymbolAddress((void**)&t3, g_t3);
    cudaGetSymbolAddress((void**)&ct, g_cos);
    cudaGetSymbolAddress((void**)&st, g_sin);
    cudaGetSymbolAddress((void**)&wt, g_wt);

    // weights -> tf32 (rounded) scratch
    cvt_w_k<<<256, 256>>>(wq, wt + WQO, DIM * DIM / 4);
    cvt_w_k<<<256, 256>>>(wk, wt + WKO, DIM * DIM / 4);
    cvt_w_k<<<256, 256>>>(wv, wt + WVO, DIM * DIM / 4);
    cvt_w_k<<<256, 256>>>(wo, wt + WOO, DIM * DIM / 4);
    cvt_w_k<<<512, 256>>>(w1, wt + W1O, HIDDEN * DIM / 4);
    cvt_w_k<<<512, 256>>>(w3, wt + W3O, HIDDEN * DIM / 4);
    cvt_w_k<<<512, 256>>>(w2, wt + W2O, DIM * HIDDEN / 4);

    rope_tables_k<<<(SEQ * 32) / 256, 256>>>(ct, st);
    rmsnorm_k<<<SEQ, 256>>>(x, ga, xn);

    // QKV batched (z = 3)
    {
        Batch3 bt;
        bt.B[0] = wt + WQO; bt.B[1] = wt + WKO; bt.B[2] = wt + WVO;
        bt.C[0] = q; bt.C[1] = k; bt.C[2] = v;
        bt.R[0] = bt.R[1] = bt.R[2] = nullptr;
        gemm_tc<false><<<dim3(DIM / BN, SEQ / BM, 3), 256>>>(xn, bt, SEQ, DIM, DIM);
    }

    rope_k<<<SEQ, 512>>>(q, k, ct, st);
    flash_attn_tc<<<dim3(SEQ / BQ, NH), 128>>>(q, k, v, at);

    // Wo + residual -> out
    {
        Batch3 bt;
        bt.B[0] = wt + WOO; bt.C[0] = out; bt.R[0] = x;
        bt.B[1] = bt.B[2] = nullptr; bt.C[1] = bt.C[2] = nullptr; bt.R[1] = bt.R[2] = nullptr;
        gemm_tc<true><<<dim3(DIM / BN, SEQ / BM, 1), 256>>>(at, bt, SEQ, DIM, DIM);
    }

    rmsnorm_k<<<SEQ, 256>>>(out, gf, hn);

    // w1 / w3 batched (z = 2)
    {
        Batch3 bt;
        bt.B[0] = wt + W1O; bt.B[1] = wt + W3O; bt.B[2] = nullptr;
        bt.C[0] = t1; bt.C[1] = t3; bt.C[2] = nullptr;
        bt.R[0] = bt.R[1] = bt.R[2] = nullptr;
        gemm_tc<false><<<dim3(HIDDEN / BN, SEQ / BM, 2), 256>>>(hn, bt, SEQ, HIDDEN, DIM);
    }

    silu_mul_k<<<(SEQ * HIDDEN / 4 + 255) / 256, 256>>>(t1, t3, SEQ * HIDDEN / 4);

    // W2 + residual -> out
    {
        Batch3 bt;
        bt.B[0] = wt + W2O; bt.C[0] = out; bt.R[0] = out;
        bt.B[1] = bt.B[2] = nullptr; bt.C[1] = bt.C[2] = nullptr; bt.R[1] = bt.R[2] = nullptr;
        gemm_tc<true><<<dim3(DIM / BN, SEQ / BM, 1), 256>>>(t1, bt, SEQ, DIM, HIDDEN);
    }
}